// round 8
// baseline (speedup 1.0000x reference)
#include <cuda_runtime.h>
#include <cuda_fp16.h>
#include <cstdint>

#define NT 256
#define ROWS 128
#define NCHUNK 16
// smem byte offsets
#define SM_A    0         // 128 rows x 264 fp16 (stride 528B)
#define SM_W1   67584     // 2 bufs x [hi 32x264 | lo 32x264]
#define W1BUF   33792
#define W1LO    16896
#define SM_W2   135168    // 2 bufs x [hi 128x40 | lo 128x40] (stride 80B)
#define W2BUF   20480
#define W2LO    10240
#define SM_H    176128    // 128 x 40 fp16 (stride 80B)
#define SM_TOTAL 186368

__device__ float g_agg[50000 * 128];
// weight images: fp16 hi/lo, chunk-contiguous
__device__ __align__(16) __half g_w1m_hi[16 * 32 * 264];
__device__ __align__(16) __half g_w1m_lo[16 * 32 * 264];
__device__ __align__(16) __half g_w2m_hi[16 * 128 * 40];
__device__ __align__(16) __half g_w2m_lo[16 * 128 * 40];
__device__ __align__(16) __half g_w1u_hi[16 * 32 * 264];
__device__ __align__(16) __half g_w1u_lo[16 * 32 * 264];
__device__ __align__(16) __half g_w2u_hi[16 * 128 * 40];
__device__ __align__(16) __half g_w2u_lo[16 * 128 * 40];

__device__ __forceinline__ uint32_t smem_u32(const void* p) {
    uint32_t a;
    asm("{ .reg .u64 t; cvta.to.shared.u64 t, %1; cvt.u32.u64 %0, t; }" : "=r"(a) : "l"(p));
    return a;
}
__device__ __forceinline__ void ldm4(uint32_t addr, uint32_t* r) {
    asm volatile("ldmatrix.sync.aligned.m8n8.x4.shared.b16 {%0,%1,%2,%3}, [%4];"
                 : "=r"(r[0]), "=r"(r[1]), "=r"(r[2]), "=r"(r[3]) : "r"(addr));
}
__device__ __forceinline__ void mma_f16(float* c, const uint32_t* a,
                                        uint32_t b0, uint32_t b1) {
    asm volatile(
        "mma.sync.aligned.m16n8k16.row.col.f32.f16.f16.f32 "
        "{%0,%1,%2,%3}, {%4,%5,%6,%7}, {%8,%9}, {%0,%1,%2,%3};"
        : "+f"(c[0]), "+f"(c[1]), "+f"(c[2]), "+f"(c[3])
        : "r"(a[0]), "r"(a[1]), "r"(a[2]), "r"(a[3]), "r"(b0), "r"(b1));
}
__device__ __forceinline__ void cp16(uint32_t dst, const void* src) {
    asm volatile("cp.async.cg.shared.global [%0], [%1], 16;" :: "r"(dst), "l"(src));
}
__device__ __forceinline__ uint32_t h2bits(__half2 v) {
    return *reinterpret_cast<uint32_t*>(&v);
}

__global__ void zero_agg_kernel(float* agg, int n4) {
    int i = blockIdx.x * blockDim.x + threadIdx.x;
    if (i < n4) ((float4*)agg)[i] = make_float4(0.f, 0.f, 0.f, 0.f);
}
// W1 [256k x 512n] -> [16 chunk(n32)][32 n][264 k] fp16 hi/lo
__global__ void prep_w1(const float* __restrict__ W, __half* hi, __half* lo) {
    int idx = blockIdx.x * blockDim.x + threadIdx.x;  // 131072
    int k = idx >> 9, n = idx & 511;
    float v = W[idx];
    __half h = __float2half_rn(v);
    int pos = (n >> 5) * 8448 + (n & 31) * 264 + k;
    hi[pos] = h;
    lo[pos] = __float2half_rn(v - __half2float(h));
}
// W2 [512k x 128n] -> [16 chunk(k32)][128 n][40 k] fp16 hi/lo
__global__ void prep_w2(const float* __restrict__ W, __half* hi, __half* lo) {
    int idx = blockIdx.x * blockDim.x + threadIdx.x;  // 65536
    int k = idx >> 7, n = idx & 127;
    float v = W[idx];
    __half h = __float2half_rn(v);
    int pos = (k >> 5) * 5120 + n * 40 + (k & 31);
    hi[pos] = h;
    lo[pos] = __float2half_rn(v - __half2float(h));
}

// one commit group per chunk: W1 hi+lo (16896B each) + W2 hi+lo (10240B each)
__device__ __forceinline__ void prefetch_chunk(uint32_t sb, int c,
        const __half* w1h, const __half* w1l,
        const __half* w2h, const __half* w2l, int tid) {
    const char* s1h = ((const char*)w1h) + c * 16896;
    const char* s1l = ((const char*)w1l) + c * 16896;
    uint32_t d1 = sb + SM_W1 + (uint32_t)(c & 1) * W1BUF;
#pragma unroll
    for (int j = 0; j < 5; ++j) {
        int idx = tid + j * NT;
        if (idx < 1056) {
            cp16(d1 + idx * 16, s1h + idx * 16);
            cp16(d1 + W1LO + idx * 16, s1l + idx * 16);
        }
    }
    const char* s2h = ((const char*)w2h) + c * 10240;
    const char* s2l = ((const char*)w2l) + c * 10240;
    uint32_t d2 = sb + SM_W2 + (uint32_t)(c & 1) * W2BUF;
#pragma unroll
    for (int j = 0; j < 3; ++j) {
        int idx = tid + j * NT;
        if (idx < 640) {
            cp16(d2 + idx * 16, s2h + idx * 16);
            cp16(d2 + W2LO + idx * 16, s2l + idx * 16);
        }
    }
    asm volatile("cp.async.commit_group;");
}

// Fused 2-layer MLP, 128 rows/CTA, fp16 A-single / W hi+lo 2-term mma.sync,
// N=32 chunks, fully double-buffered weights, prefetch-ahead-by-2.
template <bool IS_EDGE>
__global__ __launch_bounds__(NT, 1)
void mlp_mma(const float* __restrict__ x, const float* __restrict__ second,
             const int* __restrict__ eidx,
             const __half* __restrict__ w1h, const __half* __restrict__ w1l,
             const __half* __restrict__ w2h, const __half* __restrict__ w2l,
             const float* __restrict__ b1, const float* __restrict__ b2,
             float* __restrict__ out, int M, int E) {
    extern __shared__ __align__(16) unsigned char smem[];
    const uint32_t sb = smem_u32(smem);
    const int tid = threadIdx.x;
    const int lane = tid & 31;
    const int wid = tid >> 5;
    const int wm = wid & 3, wn = wid >> 2;   // 4 m-warps x 2 n-warps
    const int rowbase = blockIdx.x * ROWS;

    // two chunks of weights in flight before anything else
    prefetch_chunk(sb, 0, w1h, w1l, w2h, w2l, tid);
    prefetch_chunk(sb, 1, w1h, w1l, w2h, w2l, tid);

    // ---- gather A = [feat_i(128) | feat_j(128)] -> fp16 smem ----
    {
        int r = tid >> 1, half = tid & 1;
        int row = rowbase + r;
        const float* src;
        if (IS_EDGE) {
            int e = (row < E) ? row : 0;
            int node = half ? eidx[e] : eidx[E + e];   // half0 = i, half1 = j
            src = x + (size_t)node * 128;
        } else {
            int rr = (row < M) ? row : 0;
            src = (half ? second : x) + (size_t)rr * 128;
        }
        uint32_t abase = sb + SM_A + (uint32_t)(r * 528 + half * 256);
#pragma unroll
        for (int jj = 0; jj < 32; ++jj) {
            float4 v = *(const float4*)(src + jj * 4);
            uint32_t h0 = h2bits(__float22half2_rn(make_float2(v.x, v.y)));
            uint32_t h1 = h2bits(__float22half2_rn(make_float2(v.z, v.w)));
            asm volatile("st.shared.v2.b32 [%0], {%1,%2};"
                         :: "r"(abase + jj * 8), "r"(h0), "r"(h1) : "memory");
        }
    }

    // ldmatrix lane base addresses
    const uint32_t aB0 = sb + SM_A +
        (uint32_t)((wm * 32 + (lane & 15)) * 528 + ((lane >> 4) & 1) * 16);
    const uint32_t aB1 = aB0 + 16 * 528;
    const uint32_t bOff = (uint32_t)((wn * 16 + (lane & 7) + ((lane >> 4) & 1) * 8) * 528 +
                                     ((lane >> 3) & 1) * 16);
    const uint32_t hB0 = sb + SM_H +
        (uint32_t)((wm * 32 + (lane & 15)) * 80 + ((lane >> 4) & 1) * 16);
    const uint32_t hB1 = hB0 + 16 * 80;
    uint32_t w2Off[4];
#pragma unroll
    for (int p = 0; p < 4; ++p)
        w2Off[p] = (uint32_t)((wn * 64 + p * 16 + (lane & 7) + ((lane >> 4) & 1) * 8) * 80 +
                              ((lane >> 3) & 1) * 16);

    float acc2[64];
#pragma unroll
    for (int i = 0; i < 64; ++i) acc2[i] = 0.f;

    const int rsub = lane >> 2;        // 0..7
    const int cc = (lane & 3) * 2;

    for (int c = 0; c < NCHUNK; ++c) {
        if (c + 1 < NCHUNK) asm volatile("cp.async.wait_group 1;");
        else                asm volatile("cp.async.wait_group 0;");
        __syncthreads();   // chunk-c weights visible; GEMM2(c-1) done (H free)

        // ---- GEMM1: acc1[128 x 32chunk], K=256, D += A*(W1h + W1l) ----
        const uint32_t w1b = sb + SM_W1 + (uint32_t)(c & 1) * W1BUF;
        float acc1[16];
#pragma unroll
        for (int i = 0; i < 16; ++i) acc1[i] = 0.f;
#pragma unroll
        for (int s = 0; s < 16; ++s) {
            uint32_t ah0[4], ah1[4], bh[4], bl[4];
            ldm4(aB0 + s * 32, ah0);
            ldm4(aB1 + s * 32, ah1);
            ldm4(w1b + bOff + s * 32, bh);
            ldm4(w1b + W1LO + bOff + s * 32, bl);
            mma_f16(acc1 + 0,  ah0, bh[0], bh[1]);
            mma_f16(acc1 + 4,  ah0, bh[2], bh[3]);
            mma_f16(acc1 + 0,  ah0, bl[0], bl[1]);
            mma_f16(acc1 + 4,  ah0, bl[2], bl[3]);
            mma_f16(acc1 + 8,  ah1, bh[0], bh[1]);
            mma_f16(acc1 + 12, ah1, bh[2], bh[3]);
            mma_f16(acc1 + 8,  ah1, bl[0], bl[1]);
            mma_f16(acc1 + 12, ah1, bl[2], bl[3]);
        }

        // ---- epilogue: relu(acc1 + b1) -> fp16 H smem ----
#pragma unroll
        for (int im = 0; im < 2; ++im) {
#pragma unroll
            for (int nq = 0; nq < 2; ++nq) {
                const float* ac = acc1 + im * 8 + nq * 4;
                int gcol = c * 32 + wn * 16 + nq * 8 + cc;
                float ba = __ldg(b1 + gcol), bb = __ldg(b1 + gcol + 1);
                float v00 = fmaxf(ac[0] + ba, 0.f);
                float v01 = fmaxf(ac[1] + bb, 0.f);
                float v10 = fmaxf(ac[2] + ba, 0.f);
                float v11 = fmaxf(ac[3] + bb, 0.f);
                uint32_t p0 = h2bits(__float22half2_rn(make_float2(v00, v01)));
                uint32_t p1 = h2bits(__float22half2_rn(make_float2(v10, v11)));
                int hcol = wn * 16 + nq * 8 + cc;
                int r0 = wm * 32 + im * 16 + rsub;
                uint32_t a0 = sb + SM_H + (uint32_t)(r0 * 80 + hcol * 2);
                asm volatile("st.shared.b32 [%0], %1;" :: "r"(a0), "r"(p0) : "memory");
                asm volatile("st.shared.b32 [%0], %1;" :: "r"(a0 + 8 * 80), "r"(p1) : "memory");
            }
        }
        __syncthreads();   // H visible

        // ---- GEMM2: acc2 += H[128x32] @ (W2h+W2l)[32x128] ----
        const uint32_t w2b = sb + SM_W2 + (uint32_t)(c & 1) * W2BUF;
#pragma unroll
        for (int s = 0; s < 2; ++s) {
            uint32_t hh0[4], hh1[4];
            ldm4(hB0 + s * 32, hh0);
            ldm4(hB1 + s * 32, hh1);
#pragma unroll
            for (int p = 0; p < 4; ++p) {
                uint32_t bh[4], bl[4];
                ldm4(w2b + w2Off[p] + s * 32, bh);
                ldm4(w2b + W2LO + w2Off[p] + s * 32, bl);
                float* a0 = acc2 + p * 8;
                float* a1 = acc2 + 32 + p * 8;
                mma_f16(a0 + 0, hh0, bh[0], bh[1]);
                mma_f16(a0 + 4, hh0, bh[2], bh[3]);
                mma_f16(a0 + 0, hh0, bl[0], bl[1]);
                mma_f16(a0 + 4, hh0, bl[2], bl[3]);
                mma_f16(a1 + 0, hh1, bh[0], bh[1]);
                mma_f16(a1 + 4, hh1, bh[2], bh[3]);
                mma_f16(a1 + 0, hh1, bl[0], bl[1]);
                mma_f16(a1 + 4, hh1, bl[2], bl[3]);
            }
        }
        __syncthreads();   // chunk-c weight buffers free
        if (c + 2 < NCHUNK)
            prefetch_chunk(sb, c + 2, w1h, w1l, w2h, w2l, tid);
    }

    // ---- final epilogue: out = acc2 + b2 ----
#pragma unroll
    for (int im = 0; im < 2; ++im) {
        int e0 = rowbase + wm * 32 + im * 16 + rsub;
        int e1 = e0 + 8;
        int tgt0 = 0, tgt1 = 0;
        if (IS_EDGE) {
            tgt0 = (e0 < E) ? eidx[E + e0] : 0;
            tgt1 = (e1 < E) ? eidx[E + e1] : 0;
        }
#pragma unroll
        for (int p = 0; p < 4; ++p) {
#pragma unroll
            for (int t = 0; t < 2; ++t) {
                const float* ac = acc2 + im * 32 + p * 8 + t * 4;
                int col = wn * 64 + p * 16 + t * 8 + cc;
                float ba = __ldg(b2 + col), bb = __ldg(b2 + col + 1);
                float v00 = ac[0] + ba, v01 = ac[1] + bb;
                float v10 = ac[2] + ba, v11 = ac[3] + bb;
                if (IS_EDGE) {
                    if (e0 < E) {
                        atomicAdd(out + (size_t)tgt0 * 128 + col, v00);
                        atomicAdd(out + (size_t)tgt0 * 128 + col + 1, v01);
                    }
                    if (e1 < E) {
                        atomicAdd(out + (size_t)tgt1 * 128 + col, v10);
                        atomicAdd(out + (size_t)tgt1 * 128 + col + 1, v11);
                    }
                } else {
                    if (e0 < M) *(float2*)(out + (size_t)e0 * 128 + col) = make_float2(v00, v01);
                    if (e1 < M) *(float2*)(out + (size_t)e1 * 128 + col) = make_float2(v10, v11);
                }
            }
        }
    }
}

extern "C" void kernel_launch(void* const* d_in, const int* in_sizes, int n_in,
                              void* d_out, int out_size) {
    const float* x   = (const float*)d_in[0];
    const int* eidx  = (const int*)d_in[2];   // JAX demotes int64 -> int32
    const float* W1m = (const float*)d_in[3];
    const float* b1m = (const float*)d_in[4];
    const float* W2m = (const float*)d_in[5];
    const float* b2m = (const float*)d_in[6];
    const float* W1u = (const float*)d_in[7];
    const float* b1u = (const float*)d_in[8];
    const float* W2u = (const float*)d_in[9];
    const float* b2u = (const float*)d_in[10];
    float* out = (float*)d_out;

    int N = in_sizes[0] / 128;
    int E = in_sizes[2] / 2;

    float* agg; cudaGetSymbolAddress((void**)&agg, g_agg);
    __half *w1mh, *w1ml, *w2mh, *w2ml, *w1uh, *w1ul, *w2uh, *w2ul;
    cudaGetSymbolAddress((void**)&w1mh, g_w1m_hi);
    cudaGetSymbolAddress((void**)&w1ml, g_w1m_lo);
    cudaGetSymbolAddress((void**)&w2mh, g_w2m_hi);
    cudaGetSymbolAddress((void**)&w2ml, g_w2m_lo);
    cudaGetSymbolAddress((void**)&w1uh, g_w1u_hi);
    cudaGetSymbolAddress((void**)&w1ul, g_w1u_lo);
    cudaGetSymbolAddress((void**)&w2uh, g_w2u_hi);
    cudaGetSymbolAddress((void**)&w2ul, g_w2u_lo);

    cudaFuncSetAttribute((const void*)mlp_mma<true>,
                         cudaFuncAttributeMaxDynamicSharedMemorySize, SM_TOTAL);
    cudaFuncSetAttribute((const void*)mlp_mma<false>,
                         cudaFuncAttributeMaxDynamicSharedMemorySize, SM_TOTAL);

    int n4 = (N * 128) / 4;
    zero_agg_kernel<<<(n4 + 255) / 256, 256>>>(agg, n4);
    prep_w1<<<512, 256>>>(W1m, w1mh, w1ml);
    prep_w2<<<256, 256>>>(W2m, w2mh, w2ml);
    prep_w1<<<512, 256>>>(W1u, w1uh, w1ul);
    prep_w2<<<256, 256>>>(W2u, w2uh, w2ul);

    mlp_mma<true><<<(E + ROWS - 1) / ROWS, NT, SM_TOTAL>>>(
        x, x, eidx, w1mh, w1ml, w2mh, w2ml, b1m, b2m, agg, E, E);

    mlp_mma<false><<<(N + ROWS - 1) / ROWS, NT, SM_TOTAL>>>(
        x, agg, nullptr, w1uh, w1ul, w2uh, w2ul, b1u, b2u, out, N, 0);
}